// round 6
// baseline (speedup 1.0000x reference)
#include <cuda_runtime.h>
#include <cstdint>
#include <cstddef>

#define DK 128
#define NMAX 100000
#define MT 64            // rows per block tile
#define AP 128           // As row stride = DK (k-dim width; broadcast reads are conflict-immune)
#define GEMM_THREADS 256

// Scratch (device globals: no allocation allowed). float4-typed for 16B base alignment.
__device__ float4 g_agg_st4[(size_t)NMAX * (DK / 4)];
__device__ float4 g_agg_ts4[(size_t)NMAX * (DK / 4)];
__device__ float g_cnt_in[NMAX];
__device__ float g_cnt_out[NMAX];
__device__ float g_inv_in[NMAX];
__device__ float g_inv_out[NMAX];

__global__ void zero_kernel(int n_nodes) {
    int stride = gridDim.x * blockDim.x;
    int i0 = blockIdx.x * blockDim.x + threadIdx.x;
    int total4 = n_nodes * (DK / 4);
    float4 z = make_float4(0.f, 0.f, 0.f, 0.f);
    for (int i = i0; i < total4; i += stride) {
        g_agg_st4[i] = z;
        g_agg_ts4[i] = z;
    }
    for (int i = i0; i < n_nodes; i += stride) {
        g_cnt_in[i] = 0.f;
        g_cnt_out[i] = 0.f;
    }
}

// One warp per edge, BOTH directions. Lane l owns floats [4l, 4l+4).
// edge_index is INT32. Vector red.global.add.v4.f32: one 16B reduction
// message per lane per direction -> 4x fewer L2 atomic-ALU ops than scalar.
__global__ void scatter_kernel(const float* __restrict__ x,
                               const int* __restrict__ ei, int E) {
    int e = (int)((blockIdx.x * (unsigned)blockDim.x + threadIdx.x) >> 5);
    int lane = threadIdx.x & 31;
    if (e >= E) return;
    int s = ei[e];        // src
    int d = ei[E + e];    // dst
    float4 vs = __ldg(((const float4*)(x + (size_t)s * DK)) + lane);
    float4 vd = __ldg(((const float4*)(x + (size_t)d * DK)) + lane);
    float4* pst = g_agg_st4 + (size_t)d * (DK / 4) + lane;  // src -> dst
    float4* pts = g_agg_ts4 + (size_t)s * (DK / 4) + lane;  // dst -> src
    asm volatile("red.global.add.v4.f32 [%0], {%1, %2, %3, %4};"
                 :: "l"(pst), "f"(vs.x), "f"(vs.y), "f"(vs.z), "f"(vs.w) : "memory");
    asm volatile("red.global.add.v4.f32 [%0], {%1, %2, %3, %4};"
                 :: "l"(pts), "f"(vd.x), "f"(vd.y), "f"(vd.z), "f"(vd.w) : "memory");
    if (lane == 0) {
        atomicAdd(g_cnt_in + d, 1.0f);
        atomicAdd(g_cnt_out + s, 1.0f);
    }
}

// inv = 0.5 / max(count, 1): folds the alpha blend weight into the mean.
__global__ void inv_kernel(int n) {
    int i = blockIdx.x * blockDim.x + threadIdx.x;
    if (i < n) {
        g_inv_in[i]  = 0.5f / fmaxf(g_cnt_in[i], 1.f);
        g_inv_out[i] = 0.5f / fmaxf(g_cnt_out[i], 1.f);
    }
}

// Fused GEMM, crossbar-optimized tiling:
//   block tile 64 rows x 128 cols; thread tile 8 rows x 4 cols.
//   txc = tid&31 (col group of 4), ty = tid>>5 (warp = row group of 8).
//   k advances by 4: W = 4x LDS.128 (distinct, 4cyc ea), A = 8x LDS.128
//   warp-uniform broadcast (1 wavefront ea) -> crossbar demand ~0.75 of
//   fma-pipe time -> FMA-bound.
__global__ void __launch_bounds__(GEMM_THREADS, 2) gemm_kernel(
    const float* __restrict__ x,
    const float* __restrict__ Wlin, const float* __restrict__ Wst, const float* __restrict__ Wts,
    const float* __restrict__ blin, const float* __restrict__ bst, const float* __restrict__ bts,
    float* __restrict__ out, int N)
{
    extern __shared__ float smem[];
    float* Ws = smem;                 // [DK][DK] k-major
    float* As = smem + DK * DK;       // [MT][AP=DK] row-major
    int tid = threadIdx.x;
    int txc = tid & 31;               // 32 col groups of 4 cols
    int ty  = tid >> 5;               // 8 row groups of 8 rows (one warp each)
    int row0 = blockIdx.x * MT;

    unsigned long long acc[8][2];     // [row][colpair], packed (f32,f32)
#pragma unroll
    for (int r = 0; r < 8; r++) { acc[r][0] = 0ull; acc[r][1] = 0ull; }

#pragma unroll 1
    for (int seg = 0; seg < 3; seg++) {
        const float* W   = seg == 0 ? Wlin : (seg == 1 ? Wst : Wts);
        const float4* A4 = seg == 0 ? (const float4*)x
                                    : (seg == 1 ? (const float4*)g_agg_st4
                                                : (const float4*)g_agg_ts4);
        const float* inv = (seg == 1) ? g_inv_in : g_inv_out;
        __syncthreads();
        // Stage W: 4096 float4, 16 per thread, coalesced
#pragma unroll
        for (int i = 0; i < 16; i++) {
            int idx = tid + i * GEMM_THREADS;
            ((float4*)Ws)[idx] = __ldg(((const float4*)W) + idx);
        }
        // Stage A: 64 rows x 32 float4; lanes vary kc -> coalesced gmem,
        // STS.128 conflict-free (512 consecutive bytes per warp)
#pragma unroll
        for (int i = 0; i < 8; i++) {
            int idx = tid + i * GEMM_THREADS;
            int kc = idx & 31, r = idx >> 5;
            int rg = row0 + r;
            float4 v = make_float4(0.f, 0.f, 0.f, 0.f);
            if (rg < N) {
                v = __ldg(A4 + (size_t)rg * (DK / 4) + kc);
                if (seg) {
                    float sc = inv[rg];
                    v.x *= sc; v.y *= sc; v.z *= sc; v.w *= sc;
                }
            }
            *((float4*)(As + r * AP + (kc << 2))) = v;
        }
        __syncthreads();

#pragma unroll 2
        for (int k = 0; k < DK; k += 4) {
            // W for 4 k-steps: each ulonglong2 = 2 packed col-pairs
            ulonglong2 w0 = *((const ulonglong2*)(Ws + (k + 0) * DK + txc * 4));
            ulonglong2 w1 = *((const ulonglong2*)(Ws + (k + 1) * DK + txc * 4));
            ulonglong2 w2 = *((const ulonglong2*)(Ws + (k + 2) * DK + txc * 4));
            ulonglong2 w3 = *((const ulonglong2*)(Ws + (k + 3) * DK + txc * 4));
#pragma unroll
            for (int r = 0; r < 8; r++) {
                float4 a = *((const float4*)(As + (ty * 8 + r) * AP + k));
                unsigned long long ax, ay, az, aw;
                asm("mov.b64 %0, {%1, %1};" : "=l"(ax) : "f"(a.x));
                asm("mov.b64 %0, {%1, %1};" : "=l"(ay) : "f"(a.y));
                asm("mov.b64 %0, {%1, %1};" : "=l"(az) : "f"(a.z));
                asm("mov.b64 %0, {%1, %1};" : "=l"(aw) : "f"(a.w));
                asm("fma.rn.f32x2 %0, %1, %2, %3;" : "=l"(acc[r][0]) : "l"(ax), "l"(w0.x), "l"(acc[r][0]));
                asm("fma.rn.f32x2 %0, %1, %2, %3;" : "=l"(acc[r][1]) : "l"(ax), "l"(w0.y), "l"(acc[r][1]));
                asm("fma.rn.f32x2 %0, %1, %2, %3;" : "=l"(acc[r][0]) : "l"(ay), "l"(w1.x), "l"(acc[r][0]));
                asm("fma.rn.f32x2 %0, %1, %2, %3;" : "=l"(acc[r][1]) : "l"(ay), "l"(w1.y), "l"(acc[r][1]));
                asm("fma.rn.f32x2 %0, %1, %2, %3;" : "=l"(acc[r][0]) : "l"(az), "l"(w2.x), "l"(acc[r][0]));
                asm("fma.rn.f32x2 %0, %1, %2, %3;" : "=l"(acc[r][1]) : "l"(az), "l"(w2.y), "l"(acc[r][1]));
                asm("fma.rn.f32x2 %0, %1, %2, %3;" : "=l"(acc[r][0]) : "l"(aw), "l"(w3.x), "l"(acc[r][0]));
                asm("fma.rn.f32x2 %0, %1, %2, %3;" : "=l"(acc[r][1]) : "l"(aw), "l"(w3.y), "l"(acc[r][1]));
            }
        }
    }

    // Epilogue: combined bias + store (4 cols per thread)
    int c0 = txc * 4;
    float4 bl = __ldg((const float4*)(blin + c0));
    float4 bs = __ldg((const float4*)(bst + c0));
    float4 bt = __ldg((const float4*)(bts + c0));
    float bb0 = bl.x + 0.5f * (bs.x + bt.x);
    float bb1 = bl.y + 0.5f * (bs.y + bt.y);
    float bb2 = bl.z + 0.5f * (bs.z + bt.z);
    float bb3 = bl.w + 0.5f * (bs.w + bt.w);

#pragma unroll
    for (int r = 0; r < 8; r++) {
        int rg = row0 + ty * 8 + r;
        if (rg < N) {
            float o0, o1, o2, o3;
            asm("mov.b64 {%0, %1}, %2;" : "=f"(o0), "=f"(o1) : "l"(acc[r][0]));
            asm("mov.b64 {%0, %1}, %2;" : "=f"(o2), "=f"(o3) : "l"(acc[r][1]));
            float4 o = make_float4(o0 + bb0, o1 + bb1, o2 + bb2, o3 + bb3);
            *((float4*)(out + (size_t)rg * DK + c0)) = o;
        }
    }
}

extern "C" void kernel_launch(void* const* d_in, const int* in_sizes, int n_in,
                              void* d_out, int out_size) {
    const float* x    = (const float*)d_in[0];
    const int*   ei   = (const int*)d_in[1];      // int32
    const float* Wlin = (const float*)d_in[2];
    const float* blin = (const float*)d_in[3];
    const float* Wst  = (const float*)d_in[4];
    const float* bst  = (const float*)d_in[5];
    const float* Wts  = (const float*)d_in[6];
    const float* bts  = (const float*)d_in[7];
    float* out = (float*)d_out;
    int N = in_sizes[0] / DK;
    int E = in_sizes[1] / 2;

    zero_kernel<<<1024, 256>>>(N);

    long long total_threads = (long long)E * 32;
    int blocks = (int)((total_threads + 255) / 256);
    scatter_kernel<<<blocks, 256>>>(x, ei, E);

    inv_kernel<<<(N + 255) / 256, 256>>>(N);

    const int SMEM = (DK * DK + MT * AP) * (int)sizeof(float);
    cudaFuncSetAttribute(gemm_kernel, cudaFuncAttributeMaxDynamicSharedMemorySize, SMEM);
    gemm_kernel<<<(N + MT - 1) / MT, GEMM_THREADS, SMEM>>>(
        x, Wlin, Wst, Wts, blin, bst, bts, out, N);
}

// round 8
// speedup vs baseline: 1.1826x; 1.1826x over previous
#include <cuda_runtime.h>
#include <cuda_bf16.h>
#include <cstdint>
#include <cstddef>

#define DK 128
#define NMAX 100000

// ---------------- scratch (device globals; no allocation allowed) -------------
__device__ float4 g_agg_st4[(size_t)NMAX * (DK / 4)];
__device__ float4 g_agg_ts4[(size_t)NMAX * (DK / 4)];
__device__ float g_cnt_in[NMAX];
__device__ float g_cnt_out[NMAX];
__device__ float g_inv_in[NMAX];
__device__ float g_inv_out[NMAX];
// Split-bf16 transposed weights: [seg][n][k], 3 x 128 x 128 bf16 = 32KB each half
__device__ uint4 g_Bh4[3 * 2048];
__device__ uint4 g_Bl4[3 * 2048];
__device__ float g_bcomb[DK];

__device__ __forceinline__ uint32_t smem_u32(const void* p) {
    uint32_t a;
    asm("{ .reg .u64 t; cvta.to.shared.u64 t, %1; cvt.u32.u64 %0, t; }" : "=r"(a) : "l"(p));
    return a;
}

// ---------------- phase kernels ----------------------------------------------
__global__ void zero_kernel(int n_nodes) {
    int stride = gridDim.x * blockDim.x;
    int i0 = blockIdx.x * blockDim.x + threadIdx.x;
    int total4 = n_nodes * (DK / 4);
    float4 z = make_float4(0.f, 0.f, 0.f, 0.f);
    for (int i = i0; i < total4; i += stride) {
        g_agg_st4[i] = z;
        g_agg_ts4[i] = z;
    }
    for (int i = i0; i < n_nodes; i += stride) {
        g_cnt_in[i] = 0.f;
        g_cnt_out[i] = 0.f;
    }
}

// One warp per edge, both directions. edge_index is int32.
__global__ void scatter_kernel(const float* __restrict__ x,
                               const int* __restrict__ ei, int E) {
    int e = (int)((blockIdx.x * (unsigned)blockDim.x + threadIdx.x) >> 5);
    int lane = threadIdx.x & 31;
    if (e >= E) return;
    int s = ei[e];
    int d = ei[E + e];
    float4 vs = __ldg(((const float4*)(x + (size_t)s * DK)) + lane);
    float4 vd = __ldg(((const float4*)(x + (size_t)d * DK)) + lane);
    float4* pst = g_agg_st4 + (size_t)d * (DK / 4) + lane;
    float4* pts = g_agg_ts4 + (size_t)s * (DK / 4) + lane;
    asm volatile("red.global.add.v4.f32 [%0], {%1, %2, %3, %4};"
                 :: "l"(pst), "f"(vs.x), "f"(vs.y), "f"(vs.z), "f"(vs.w) : "memory");
    asm volatile("red.global.add.v4.f32 [%0], {%1, %2, %3, %4};"
                 :: "l"(pts), "f"(vd.x), "f"(vd.y), "f"(vd.z), "f"(vd.w) : "memory");
    if (lane == 0) {
        atomicAdd(g_cnt_in + d, 1.0f);
        atomicAdd(g_cnt_out + s, 1.0f);
    }
}

__global__ void inv_kernel(int n) {
    int i = blockIdx.x * blockDim.x + threadIdx.x;
    if (i < n) {
        g_inv_in[i]  = 0.5f / fmaxf(g_cnt_in[i], 1.f);
        g_inv_out[i] = 0.5f / fmaxf(g_cnt_out[i], 1.f);
    }
}

// Transpose + split W into bf16 hi/lo [seg][n][k]; combined bias.
__global__ void prep_kernel(const float* __restrict__ Wlin, const float* __restrict__ Wst,
                            const float* __restrict__ Wts, const float* __restrict__ blin,
                            const float* __restrict__ bst, const float* __restrict__ bts) {
    int idx = blockIdx.x * blockDim.x + threadIdx.x;
    if (idx < DK) g_bcomb[idx] = blin[idx] + 0.5f * (bst[idx] + bts[idx]);
    if (idx >= 3 * DK * DK) return;
    int seg = idx >> 14;
    int rem = idx & 16383;
    int n = rem >> 7, k = rem & 127;
    const float* W = seg == 0 ? Wlin : (seg == 1 ? Wst : Wts);
    float v = W[k * DK + n];                 // B[n][k] = W[k][n]
    __nv_bfloat16 h = __float2bfloat16_rn(v);
    __nv_bfloat16 l = __float2bfloat16_rn(v - __bfloat162float(h));
    ((__nv_bfloat16*)g_Bh4)[idx] = h;        // idx == seg*16384 + n*128 + k
    ((__nv_bfloat16*)g_Bl4)[idx] = l;
}

// ---------------- mma.sync split-bf16 GEMM ------------------------------------
// Per CTA: 128 rows x 128 cols; K = 3 segments x 128.
// Smem tiles: 272B row stride -> ldmatrix 8-row phases hit disjoint bank granules.
#define ROWSTR 272
#define SM_AH 0
#define SM_AL 34816
#define SM_BH 69632
#define SM_BL 104448
#define SM_TOT 139264

#define LDSM4(r0, r1, r2, r3, a) \
    asm volatile("ldmatrix.sync.aligned.m8n8.x4.shared.b16 {%0,%1,%2,%3}, [%4];" \
                 : "=r"(r0), "=r"(r1), "=r"(r2), "=r"(r3) : "r"(a))

#define MMA16816(c, a, b0, b1) \
    asm volatile("mma.sync.aligned.m16n8k16.row.col.f32.bf16.bf16.f32 " \
                 "{%0,%1,%2,%3}, {%4,%5,%6,%7}, {%8,%9}, {%0,%1,%2,%3};" \
                 : "+f"((c)[0]), "+f"((c)[1]), "+f"((c)[2]), "+f"((c)[3]) \
                 : "r"((a)[0]), "r"((a)[1]), "r"((a)[2]), "r"((a)[3]), "r"(b0), "r"(b1))

__global__ void __launch_bounds__(256) gemm_mma_kernel(
    const float* __restrict__ x, float* __restrict__ out, int N)
{
    extern __shared__ char smem[];
    uint32_t sb = smem_u32(smem);
    int tid = threadIdx.x;
    int wid = tid >> 5;
    int lane = tid & 31;
    int wy = wid >> 1;            // M chunk: rows wy*32 .. +31
    int wx = wid & 1;             // N chunk: cols wx*64 .. +63
    int row0 = blockIdx.x * 128;

    float acc[2][8][4];           // [m-tile][n-tile][frag]
#pragma unroll
    for (int m = 0; m < 2; m++)
#pragma unroll
        for (int n = 0; n < 8; n++)
#pragma unroll
            for (int q = 0; q < 4; q++) acc[m][n][q] = 0.f;

#pragma unroll 1
    for (int seg = 0; seg < 3; seg++) {
        __syncthreads();          // previous iter's smem reads complete
        // --- stage B (pre-split bf16, linear rows -> padded rows) ---
        const uint4* bh = g_Bh4 + seg * 2048;
        const uint4* bl = g_Bl4 + seg * 2048;
#pragma unroll
        for (int i = 0; i < 8; i++) {
            int idx = tid + i * 256;
            int n = idx >> 4, j = idx & 15;
            *(uint4*)(smem + SM_BH + n * ROWSTR + j * 16) = __ldg(bh + idx);
            *(uint4*)(smem + SM_BL + n * ROWSTR + j * 16) = __ldg(bl + idx);
        }
        // --- stage A: f32 -> bf16 hi/lo, inv folded ---
        const float* Asrc = seg == 0 ? x : (seg == 1 ? (const float*)g_agg_st4
                                                     : (const float*)g_agg_ts4);
        const float* inv = (seg == 1) ? g_inv_in : g_inv_out;
#pragma unroll
        for (int i = 0; i < 32; i++) {
            int p = tid + i * 256;          // 128 rows x 64 float2
            int r = p >> 6, cp = p & 63;
            int rg = row0 + r;
            float v0 = 0.f, v1 = 0.f;
            if (rg < N) {
                float2 val = __ldg((const float2*)(Asrc + (size_t)rg * DK) + cp);
                float sc = seg ? inv[rg] : 1.0f;
                v0 = val.x * sc;
                v1 = val.y * sc;
            }
            __nv_bfloat162 hp = __floats2bfloat162_rn(v0, v1);
            float h0 = __bfloat162float(__low2bfloat16(hp));
            float h1 = __bfloat162float(__high2bfloat16(hp));
            __nv_bfloat162 lp = __floats2bfloat162_rn(v0 - h0, v1 - h1);
            *(uint32_t*)(smem + SM_AH + r * ROWSTR + cp * 4) = *(uint32_t*)&hp;
            *(uint32_t*)(smem + SM_AL + r * ROWSTR + cp * 4) = *(uint32_t*)&lp;
        }
        __syncthreads();

        // --- mainloop: 8 k-tiles x (2 m-tiles x 8 n-tiles) x 3 split terms ---
#pragma unroll 1
        for (int kt = 0; kt < 8; kt++) {
            uint32_t ah[2][4], al[2][4];
#pragma unroll
            for (int mt = 0; mt < 2; mt++) {
                int row = wy * 32 + mt * 16 + (lane & 7) + ((lane >> 3) & 1) * 8;
                uint32_t a_hi = sb + SM_AH + row * ROWSTR + kt * 32 + (lane >> 4) * 16;
                LDSM4(ah[mt][0], ah[mt][1], ah[mt][2], ah[mt][3], a_hi);
                uint32_t a_lo = a_hi + (SM_AL - SM_AH);
                LDSM4(al[mt][0], al[mt][1], al[mt][2], al[mt][3], a_lo);
            }
#pragma unroll
            for (int ntp = 0; ntp < 4; ntp++) {
                int nrow = wx * 64 + ntp * 16 + (lane & 7) + (lane >> 4) * 8;
                uint32_t b_hi = sb + SM_BH + nrow * ROWSTR + kt * 32 + ((lane >> 3) & 1) * 16;
                uint32_t bh0, bh1, bh2, bh3, bl0, bl1, bl2, bl3;
                LDSM4(bh0, bh1, bh2, bh3, b_hi);
                uint32_t b_lo = b_hi + (SM_BL - SM_BH);
                LDSM4(bl0, bl1, bl2, bl3, b_lo);
#pragma unroll
                for (int mt = 0; mt < 2; mt++) {
                    MMA16816(acc[mt][ntp * 2 + 0], ah[mt], bh0, bh1);
                    MMA16816(acc[mt][ntp * 2 + 0], ah[mt], bl0, bl1);
                    MMA16816(acc[mt][ntp * 2 + 0], al[mt], bh0, bh1);
                    MMA16816(acc[mt][ntp * 2 + 1], ah[mt], bh2, bh3);
                    MMA16816(acc[mt][ntp * 2 + 1], ah[mt], bl2, bl3);
                    MMA16816(acc[mt][ntp * 2 + 1], al[mt], bh2, bh3);
                }
            }
        }
    }

    // --- epilogue: bias + store. d0,d1 -> row l/4; d2,d3 -> row l/4+8 ---
#pragma unroll
    for (int mt = 0; mt < 2; mt++) {
        int rbase = row0 + wy * 32 + mt * 16 + (lane >> 2);
#pragma unroll
        for (int dd = 0; dd < 2; dd++) {
            int rg = rbase + dd * 8;
            if (rg < N) {
                float* orow = out + (size_t)rg * DK;
#pragma unroll
                for (int nt = 0; nt < 8; nt++) {
                    int c = wx * 64 + nt * 8 + (lane & 3) * 2;
                    float2 bb = *(const float2*)(g_bcomb + c);
                    float2 o;
                    o.x = acc[mt][nt][dd * 2 + 0] + bb.x;
                    o.y = acc[mt][nt][dd * 2 + 1] + bb.y;
                    *(float2*)(orow + c) = o;
                }
            }
        }
    }
}

// ---------------- host launch --------------------------------------------------
extern "C" void kernel_launch(void* const* d_in, const int* in_sizes, int n_in,
                              void* d_out, int out_size) {
    const float* x    = (const float*)d_in[0];
    const int*   ei   = (const int*)d_in[1];      // int32
    const float* Wlin = (const float*)d_in[2];
    const float* blin = (const float*)d_in[3];
    const float* Wst  = (const float*)d_in[4];
    const float* bst  = (const float*)d_in[5];
    const float* Wts  = (const float*)d_in[6];
    const float* bts  = (const float*)d_in[7];
    float* out = (float*)d_out;
    int N = in_sizes[0] / DK;
    int E = in_sizes[1] / 2;

    zero_kernel<<<1024, 256>>>(N);

    long long total_threads = (long long)E * 32;
    int blocks = (int)((total_threads + 255) / 256);
    scatter_kernel<<<blocks, 256>>>(x, ei, E);

    inv_kernel<<<(N + 255) / 256, 256>>>(N);

    prep_kernel<<<(3 * DK * DK + 255) / 256, 256>>>(Wlin, Wst, Wts, blin, bst, bts);

    cudaFuncSetAttribute(gemm_mma_kernel, cudaFuncAttributeMaxDynamicSharedMemorySize, SM_TOT);
    gemm_mma_kernel<<<(N + 127) / 128, 256, SM_TOT>>>(x, out, N);
}

// round 9
// speedup vs baseline: 1.5784x; 1.3347x over previous
#include <cuda_runtime.h>
#include <cuda_bf16.h>
#include <cstdint>
#include <cstddef>

#define DK 128
#define NMAX 100000

// ---------------- scratch (device globals; no allocation allowed) -------------
__device__ float4 g_agg_st4[(size_t)NMAX * (DK / 4)];
__device__ float4 g_agg_ts4[(size_t)NMAX * (DK / 4)];
__device__ float g_cnt_in[NMAX];
__device__ float g_cnt_out[NMAX];
__device__ float g_inv_in[NMAX];
__device__ float g_inv_out[NMAX];
// Split-bf16 transposed weights: [seg][n][k], 3 x 128 x 128 bf16 = 32KB each half
__device__ uint4 g_Bh4[3 * 2048];
__device__ uint4 g_Bl4[3 * 2048];
__device__ float g_bcomb[DK];

__device__ __forceinline__ uint32_t smem_u32(const void* p) {
    uint32_t a;
    asm("{ .reg .u64 t; cvta.to.shared.u64 t, %1; cvt.u32.u64 %0, t; }" : "=r"(a) : "l"(p));
    return a;
}

// ---------------- phase kernels ----------------------------------------------
__global__ void zero_kernel(int n_nodes) {
    int stride = gridDim.x * blockDim.x;
    int i0 = blockIdx.x * blockDim.x + threadIdx.x;
    int total4 = n_nodes * (DK / 4);
    float4 z = make_float4(0.f, 0.f, 0.f, 0.f);
    for (int i = i0; i < total4; i += stride) {
        g_agg_st4[i] = z;
        g_agg_ts4[i] = z;
    }
    for (int i = i0; i < n_nodes; i += stride) {
        g_cnt_in[i] = 0.f;
        g_cnt_out[i] = 0.f;
    }
}

// One warp per edge, both directions. edge_index is int32.
__global__ void scatter_kernel(const float* __restrict__ x,
                               const int* __restrict__ ei, int E) {
    int e = (int)((blockIdx.x * (unsigned)blockDim.x + threadIdx.x) >> 5);
    int lane = threadIdx.x & 31;
    if (e >= E) return;
    int s = ei[e];
    int d = ei[E + e];
    float4 vs = __ldg(((const float4*)(x + (size_t)s * DK)) + lane);
    float4 vd = __ldg(((const float4*)(x + (size_t)d * DK)) + lane);
    float4* pst = g_agg_st4 + (size_t)d * (DK / 4) + lane;
    float4* pts = g_agg_ts4 + (size_t)s * (DK / 4) + lane;
    asm volatile("red.global.add.v4.f32 [%0], {%1, %2, %3, %4};"
                 :: "l"(pst), "f"(vs.x), "f"(vs.y), "f"(vs.z), "f"(vs.w) : "memory");
    asm volatile("red.global.add.v4.f32 [%0], {%1, %2, %3, %4};"
                 :: "l"(pts), "f"(vd.x), "f"(vd.y), "f"(vd.z), "f"(vd.w) : "memory");
    if (lane == 0) {
        atomicAdd(g_cnt_in + d, 1.0f);
        atomicAdd(g_cnt_out + s, 1.0f);
    }
}

// Merged: inverse-degree + W transpose/split + combined bias (one launch ->
// 4 launches/replay so ncu's -s window lands on the gemm).
__global__ void inv_prep_kernel(int n,
                                const float* __restrict__ Wlin, const float* __restrict__ Wst,
                                const float* __restrict__ Wts, const float* __restrict__ blin,
                                const float* __restrict__ bst, const float* __restrict__ bts) {
    int idx = blockIdx.x * blockDim.x + threadIdx.x;
    if (idx < n) {
        g_inv_in[idx]  = 0.5f / fmaxf(g_cnt_in[idx], 1.f);
        g_inv_out[idx] = 0.5f / fmaxf(g_cnt_out[idx], 1.f);
    }
    if (idx < DK) g_bcomb[idx] = blin[idx] + 0.5f * (bst[idx] + bts[idx]);
    if (idx >= 3 * DK * DK) return;
    int seg = idx >> 14;
    int rem = idx & 16383;
    int nn = rem >> 7, k = rem & 127;
    const float* W = seg == 0 ? Wlin : (seg == 1 ? Wst : Wts);
    float v = W[k * DK + nn];                // B[n][k] = W[k][n]
    __nv_bfloat16 h = __float2bfloat16_rn(v);
    __nv_bfloat16 l = __float2bfloat16_rn(v - __bfloat162float(h));
    ((__nv_bfloat16*)g_Bh4)[idx] = h;
    ((__nv_bfloat16*)g_Bl4)[idx] = l;
}

// ---------------- mma.sync split-bf16 GEMM ------------------------------------
// Per CTA: 128 rows x 128 cols; K = 3 segments x 128. 512 threads = 16 warps,
// warp grid 4(M) x 4(N): 4 warps/SMSP for latency hiding.
#define ROWSTR 272
#define SM_AH 0
#define SM_AL 34816
#define SM_BH 69632
#define SM_BL 104448
#define SM_TOT 139264
#define GT 512

#define LDSM4(r0, r1, r2, r3, a) \
    asm volatile("ldmatrix.sync.aligned.m8n8.x4.shared.b16 {%0,%1,%2,%3}, [%4];" \
                 : "=r"(r0), "=r"(r1), "=r"(r2), "=r"(r3) : "r"(a))

#define MMA16816(c, a, b0, b1) \
    asm volatile("mma.sync.aligned.m16n8k16.row.col.f32.bf16.bf16.f32 " \
                 "{%0,%1,%2,%3}, {%4,%5,%6,%7}, {%8,%9}, {%0,%1,%2,%3};" \
                 : "+f"((c)[0]), "+f"((c)[1]), "+f"((c)[2]), "+f"((c)[3]) \
                 : "r"((a)[0]), "r"((a)[1]), "r"((a)[2]), "r"((a)[3]), "r"(b0), "r"(b1))

__global__ void __launch_bounds__(GT) gemm_mma_kernel(
    const float* __restrict__ x, float* __restrict__ out, int N)
{
    extern __shared__ char smem[];
    uint32_t sb = smem_u32(smem);
    int tid = threadIdx.x;
    int wid = tid >> 5;
    int lane = tid & 31;
    int wy = wid >> 2;            // M chunk: rows wy*32 .. +31
    int wx = wid & 3;             // N chunk: cols wx*32 .. +31
    int row0 = blockIdx.x * 128;

    float acc[2][4][4];           // [m-tile(16)][n-tile(8)][frag]
#pragma unroll
    for (int m = 0; m < 2; m++)
#pragma unroll
        for (int n = 0; n < 4; n++)
#pragma unroll
            for (int q = 0; q < 4; q++) acc[m][n][q] = 0.f;

#pragma unroll 1
    for (int seg = 0; seg < 3; seg++) {
        __syncthreads();          // previous iter's smem reads complete
        // --- stage B (pre-split bf16, linear rows -> padded rows) ---
        const uint4* bh = g_Bh4 + seg * 2048;
        const uint4* bl = g_Bl4 + seg * 2048;
#pragma unroll
        for (int i = 0; i < 4; i++) {
            int idx = tid + i * GT;
            int n = idx >> 4, j = idx & 15;
            *(uint4*)(smem + SM_BH + n * ROWSTR + j * 16) = __ldg(bh + idx);
            *(uint4*)(smem + SM_BL + n * ROWSTR + j * 16) = __ldg(bl + idx);
        }
        // --- stage A: f32 -> bf16 hi/lo, inv folded ---
        const float* Asrc = seg == 0 ? x : (seg == 1 ? (const float*)g_agg_st4
                                                     : (const float*)g_agg_ts4);
        const float* inv = (seg == 1) ? g_inv_in : g_inv_out;
#pragma unroll
        for (int i = 0; i < 16; i++) {
            int p = tid + i * GT;           // 128 rows x 64 float2
            int r = p >> 6, cp = p & 63;
            int rg = row0 + r;
            float v0 = 0.f, v1 = 0.f;
            if (rg < N) {
                float2 val = __ldg((const float2*)(Asrc + (size_t)rg * DK) + cp);
                float sc = seg ? inv[rg] : 1.0f;
                v0 = val.x * sc;
                v1 = val.y * sc;
            }
            __nv_bfloat162 hp = __floats2bfloat162_rn(v0, v1);
            float h0 = __bfloat162float(__low2bfloat16(hp));
            float h1 = __bfloat162float(__high2bfloat16(hp));
            __nv_bfloat162 lp = __floats2bfloat162_rn(v0 - h0, v1 - h1);
            *(uint32_t*)(smem + SM_AH + r * ROWSTR + cp * 4) = *(uint32_t*)&hp;
            *(uint32_t*)(smem + SM_AL + r * ROWSTR + cp * 4) = *(uint32_t*)&lp;
        }
        __syncthreads();

        // --- mainloop: 8 k-tiles x (2 m-tiles x 4 n-tiles) x 3 split terms ---
#pragma unroll 1
        for (int kt = 0; kt < 8; kt++) {
            uint32_t ah[2][4], al[2][4];
#pragma unroll
            for (int mt = 0; mt < 2; mt++) {
                int row = wy * 32 + mt * 16 + (lane & 7) + ((lane >> 3) & 1) * 8;
                uint32_t a_hi = sb + SM_AH + row * ROWSTR + kt * 32 + (lane >> 4) * 16;
                LDSM4(ah[mt][0], ah[mt][1], ah[mt][2], ah[mt][3], a_hi);
                uint32_t a_lo = a_hi + (SM_AL - SM_AH);
                LDSM4(al[mt][0], al[mt][1], al[mt][2], al[mt][3], a_lo);
            }
#pragma unroll
            for (int ntp = 0; ntp < 2; ntp++) {
                int nrow = wx * 32 + ntp * 16 + (lane & 7) + (lane >> 4) * 8;
                uint32_t b_hi = sb + SM_BH + nrow * ROWSTR + kt * 32 + ((lane >> 3) & 1) * 16;
                uint32_t bh0, bh1, bh2, bh3, bl0, bl1, bl2, bl3;
                LDSM4(bh0, bh1, bh2, bh3, b_hi);
                uint32_t b_lo = b_hi + (SM_BL - SM_BH);
                LDSM4(bl0, bl1, bl2, bl3, b_lo);
#pragma unroll
                for (int mt = 0; mt < 2; mt++) {
                    MMA16816(acc[mt][ntp * 2 + 0], ah[mt], bh0, bh1);
                    MMA16816(acc[mt][ntp * 2 + 0], ah[mt], bl0, bl1);
                    MMA16816(acc[mt][ntp * 2 + 0], al[mt], bh0, bh1);
                    MMA16816(acc[mt][ntp * 2 + 1], ah[mt], bh2, bh3);
                    MMA16816(acc[mt][ntp * 2 + 1], ah[mt], bl2, bl3);
                    MMA16816(acc[mt][ntp * 2 + 1], al[mt], bh2, bh3);
                }
            }
        }
    }

    // --- epilogue: bias + store. d0,d1 -> row l/4; d2,d3 -> row l/4+8 ---
#pragma unroll
    for (int mt = 0; mt < 2; mt++) {
        int rbase = row0 + wy * 32 + mt * 16 + (lane >> 2);
#pragma unroll
        for (int dd = 0; dd < 2; dd++) {
            int rg = rbase + dd * 8;
            if (rg < N) {
                float* orow = out + (size_t)rg * DK;
#pragma unroll
                for (int nt = 0; nt < 4; nt++) {
                    int c = wx * 32 + nt * 8 + (lane & 3) * 2;
                    float2 bb = *(const float2*)(g_bcomb + c);
                    float2 o;
                    o.x = acc[mt][nt][dd * 2 + 0] + bb.x;
                    o.y = acc[mt][nt][dd * 2 + 1] + bb.y;
                    *(float2*)(orow + c) = o;
                }
            }
        }
    }
}

// ---------------- host launch --------------------------------------------------
extern "C" void kernel_launch(void* const* d_in, const int* in_sizes, int n_in,
                              void* d_out, int out_size) {
    const float* x    = (const float*)d_in[0];
    const int*   ei   = (const int*)d_in[1];      // int32
    const float* Wlin = (const float*)d_in[2];
    const float* blin = (const float*)d_in[3];
    const float* Wst  = (const float*)d_in[4];
    const float* bst  = (const float*)d_in[5];
    const float* Wts  = (const float*)d_in[6];
    const float* bts  = (const float*)d_in[7];
    float* out = (float*)d_out;
    int N = in_sizes[0] / DK;
    int E = in_sizes[1] / 2;

    zero_kernel<<<1024, 256>>>(N);

    long long total_threads = (long long)E * 32;
    int blocks = (int)((total_threads + 255) / 256);
    scatter_kernel<<<blocks, 256>>>(x, ei, E);

    int ip_n = (3 * DK * DK > NMAX) ? 3 * DK * DK : NMAX;
    inv_prep_kernel<<<(ip_n + 255) / 256, 256>>>(N, Wlin, Wst, Wts, blin, bst, bts);

    cudaFuncSetAttribute(gemm_mma_kernel, cudaFuncAttributeMaxDynamicSharedMemorySize, SM_TOT);
    gemm_mma_kernel<<<(N + 127) / 128, GT, SM_TOT>>>(x, out, N);
}

// round 10
// speedup vs baseline: 1.9546x; 1.2383x over previous
#include <cuda_runtime.h>
#include <cuda_bf16.h>
#include <cstdint>
#include <cstddef>

#define DK 128
#define NMAX 100000

// ---------------- scratch (device globals; no allocation allowed) -------------
__device__ float4 g_agg_st4[(size_t)NMAX * (DK / 4)];
__device__ float4 g_agg_ts4[(size_t)NMAX * (DK / 4)];
__device__ float g_cnt_in[NMAX];
__device__ float g_cnt_out[NMAX];
__device__ float g_inv_in[NMAX];
__device__ float g_inv_out[NMAX];
// Split-bf16 transposed weights: [seg][n][k], 3 x 128 x 128 bf16 = 32KB each half
__device__ uint4 g_Bh4[3 * 2048];
__device__ uint4 g_Bl4[3 * 2048];
__device__ float g_bcomb[DK];

__device__ __forceinline__ uint32_t smem_u32(const void* p) {
    uint32_t a;
    asm("{ .reg .u64 t; cvta.to.shared.u64 t, %1; cvt.u32.u64 %0, t; }" : "=r"(a) : "l"(p));
    return a;
}

// ---------------- phase kernels ----------------------------------------------
__global__ void zero_kernel(int n_nodes) {
    int stride = gridDim.x * blockDim.x;
    int i0 = blockIdx.x * blockDim.x + threadIdx.x;
    int total4 = n_nodes * (DK / 4);
    float4 z = make_float4(0.f, 0.f, 0.f, 0.f);
    for (int i = i0; i < total4; i += stride) {
        g_agg_st4[i] = z;
        g_agg_ts4[i] = z;
    }
    for (int i = i0; i < n_nodes; i += stride) {
        g_cnt_in[i] = 0.f;
        g_cnt_out[i] = 0.f;
    }
}

// One warp per edge, both directions. edge_index is int32.
__global__ void scatter_kernel(const float* __restrict__ x,
                               const int* __restrict__ ei, int E) {
    int e = (int)((blockIdx.x * (unsigned)blockDim.x + threadIdx.x) >> 5);
    int lane = threadIdx.x & 31;
    if (e >= E) return;
    int s = ei[e];
    int d = ei[E + e];
    float4 vs = __ldg(((const float4*)(x + (size_t)s * DK)) + lane);
    float4 vd = __ldg(((const float4*)(x + (size_t)d * DK)) + lane);
    float4* pst = g_agg_st4 + (size_t)d * (DK / 4) + lane;
    float4* pts = g_agg_ts4 + (size_t)s * (DK / 4) + lane;
    asm volatile("red.global.add.v4.f32 [%0], {%1, %2, %3, %4};"
                 :: "l"(pst), "f"(vs.x), "f"(vs.y), "f"(vs.z), "f"(vs.w) : "memory");
    asm volatile("red.global.add.v4.f32 [%0], {%1, %2, %3, %4};"
                 :: "l"(pts), "f"(vd.x), "f"(vd.y), "f"(vd.z), "f"(vd.w) : "memory");
    if (lane == 0) {
        atomicAdd(g_cnt_in + d, 1.0f);
        atomicAdd(g_cnt_out + s, 1.0f);
    }
}

// Merged: inverse-degree + W transpose/split + combined bias.
__global__ void inv_prep_kernel(int n,
                                const float* __restrict__ Wlin, const float* __restrict__ Wst,
                                const float* __restrict__ Wts, const float* __restrict__ blin,
                                const float* __restrict__ bst, const float* __restrict__ bts) {
    int idx = blockIdx.x * blockDim.x + threadIdx.x;
    if (idx < n) {
        g_inv_in[idx]  = 0.5f / fmaxf(g_cnt_in[idx], 1.f);
        g_inv_out[idx] = 0.5f / fmaxf(g_cnt_out[idx], 1.f);
    }
    if (idx < DK) g_bcomb[idx] = blin[idx] + 0.5f * (bst[idx] + bts[idx]);
    if (idx >= 3 * DK * DK) return;
    int seg = idx >> 14;
    int rem = idx & 16383;
    int nn = rem >> 7, k = rem & 127;
    const float* W = seg == 0 ? Wlin : (seg == 1 ? Wst : Wts);
    float v = W[k * DK + nn];                // B[n][k] = W[k][n]
    __nv_bfloat16 h = __float2bfloat16_rn(v);
    __nv_bfloat16 l = __float2bfloat16_rn(v - __bfloat162float(h));
    ((__nv_bfloat16*)g_Bh4)[idx] = h;
    ((__nv_bfloat16*)g_Bl4)[idx] = l;
}

// ---------------- mma.sync split-bf16 GEMM ------------------------------------
// Per CTA: 64 rows x 128 cols; K = 3 segments x 128. 512 threads = 16 warps,
// warp grid 2(M, 32 rows) x 8(N, 16 cols). smem 102KB -> 2 CTAs/SM (32 warps,
// occ 50%), at the cost of a 64-reg/thread cap.
#define MT 64
#define ROWSTR 272
#define SM_AH 0
#define SM_AL 17408
#define SM_BH 34816
#define SM_BL 69632
#define SM_TOT 104448
#define GT 512

#define LDSM4(r0, r1, r2, r3, a) \
    asm volatile("ldmatrix.sync.aligned.m8n8.x4.shared.b16 {%0,%1,%2,%3}, [%4];" \
                 : "=r"(r0), "=r"(r1), "=r"(r2), "=r"(r3) : "r"(a))

#define MMA16816(c, a, b0, b1) \
    asm volatile("mma.sync.aligned.m16n8k16.row.col.f32.bf16.bf16.f32 " \
                 "{%0,%1,%2,%3}, {%4,%5,%6,%7}, {%8,%9}, {%0,%1,%2,%3};" \
                 : "+f"((c)[0]), "+f"((c)[1]), "+f"((c)[2]), "+f"((c)[3]) \
                 : "r"((a)[0]), "r"((a)[1]), "r"((a)[2]), "r"((a)[3]), "r"(b0), "r"(b1))

__global__ void __launch_bounds__(GT, 2) gemm_mma_kernel(
    const float* __restrict__ x, float* __restrict__ out, int N)
{
    extern __shared__ char smem[];
    uint32_t sb = smem_u32(smem);
    int tid = threadIdx.x;
    int wid = tid >> 5;
    int lane = tid & 31;
    int wy = wid >> 3;            // M chunk: rows wy*32 .. +31
    int wxn = wid & 7;            // N chunk: cols wxn*16 .. +15
    int row0 = blockIdx.x * MT;

    float acc[2][2][4];           // [m-tile(16)][n-tile(8)][frag]
#pragma unroll
    for (int m = 0; m < 2; m++)
#pragma unroll
        for (int n = 0; n < 2; n++)
#pragma unroll
            for (int q = 0; q < 4; q++) acc[m][n][q] = 0.f;

#pragma unroll 1
    for (int seg = 0; seg < 3; seg++) {
        __syncthreads();          // previous iter's smem reads complete
        // --- stage B (pre-split bf16, linear rows -> padded rows) ---
        const uint4* bh = g_Bh4 + seg * 2048;
        const uint4* bl = g_Bl4 + seg * 2048;
#pragma unroll
        for (int i = 0; i < 4; i++) {
            int idx = tid + i * GT;
            int n = idx >> 4, j = idx & 15;
            *(uint4*)(smem + SM_BH + n * ROWSTR + j * 16) = __ldg(bh + idx);
            *(uint4*)(smem + SM_BL + n * ROWSTR + j * 16) = __ldg(bl + idx);
        }
        // --- stage A: f32 -> bf16 hi/lo, inv folded (64 rows x 64 float2) ---
        const float* Asrc = seg == 0 ? x : (seg == 1 ? (const float*)g_agg_st4
                                                     : (const float*)g_agg_ts4);
        const float* inv = (seg == 1) ? g_inv_in : g_inv_out;
#pragma unroll
        for (int i = 0; i < 8; i++) {
            int p = tid + i * GT;
            int r = p >> 6, cp = p & 63;
            int rg = row0 + r;
            float v0 = 0.f, v1 = 0.f;
            if (rg < N) {
                float2 val = __ldg((const float2*)(Asrc + (size_t)rg * DK) + cp);
                float sc = seg ? inv[rg] : 1.0f;
                v0 = val.x * sc;
                v1 = val.y * sc;
            }
            __nv_bfloat162 hp = __floats2bfloat162_rn(v0, v1);
            float h0 = __bfloat162float(__low2bfloat16(hp));
            float h1 = __bfloat162float(__high2bfloat16(hp));
            __nv_bfloat162 lp = __floats2bfloat162_rn(v0 - h0, v1 - h1);
            *(uint32_t*)(smem + SM_AH + r * ROWSTR + cp * 4) = *(uint32_t*)&hp;
            *(uint32_t*)(smem + SM_AL + r * ROWSTR + cp * 4) = *(uint32_t*)&lp;
        }
        __syncthreads();

        // --- mainloop: 8 k-tiles; per kt: B frags then per-mt A frags + 6 MMAs
        //     (ordering keeps peak live registers under the 64-reg cap) ---
#pragma unroll 1
        for (int kt = 0; kt < 8; kt++) {
            int nrow = wxn * 16 + (lane & 7) + (lane >> 4) * 8;
            uint32_t b_hi = sb + SM_BH + nrow * ROWSTR + kt * 32 + ((lane >> 3) & 1) * 16;
            uint32_t bh0, bh1, bh2, bh3, bl0, bl1, bl2, bl3;
            LDSM4(bh0, bh1, bh2, bh3, b_hi);
            LDSM4(bl0, bl1, bl2, bl3, b_hi + (SM_BL - SM_BH));
#pragma unroll
            for (int mt = 0; mt < 2; mt++) {
                int row = wy * 32 + mt * 16 + (lane & 7) + ((lane >> 3) & 1) * 8;
                uint32_t a_hi = sb + SM_AH + row * ROWSTR + kt * 32 + (lane >> 4) * 16;
                uint32_t ah[4], al[4];
                LDSM4(ah[0], ah[1], ah[2], ah[3], a_hi);
                LDSM4(al[0], al[1], al[2], al[3], a_hi + (SM_AL - SM_AH));
                MMA16816(acc[mt][0], ah, bh0, bh1);
                MMA16816(acc[mt][0], ah, bl0, bl1);
                MMA16816(acc[mt][0], al, bh0, bh1);
                MMA16816(acc[mt][1], ah, bh2, bh3);
                MMA16816(acc[mt][1], ah, bl2, bl3);
                MMA16816(acc[mt][1], al, bh2, bh3);
            }
        }
    }

    // --- epilogue: bias + store. d0,d1 -> row l/4; d2,d3 -> row l/4+8 ---
#pragma unroll
    for (int mt = 0; mt < 2; mt++) {
        int rbase = row0 + wy * 32 + mt * 16 + (lane >> 2);
#pragma unroll
        for (int dd = 0; dd < 2; dd++) {
            int rg = rbase + dd * 8;
            if (rg < N) {
                float* orow = out + (size_t)rg * DK;
#pragma unroll
                for (int nt = 0; nt < 2; nt++) {
                    int c = wxn * 16 + nt * 8 + (lane & 3) * 2;
                    float2 bb = *(const float2*)(g_bcomb + c);
                    float2 o;
                    o.x = acc[mt][nt][dd * 2 + 0] + bb.x;
                    o.y = acc[mt][nt][dd * 2 + 1] + bb.y;
                    *(float2*)(orow + c) = o;
                }
            }
        }
    }
}

// ---------------- host launch --------------------------------------------------
extern "C" void kernel_launch(void* const* d_in, const int* in_sizes, int n_in,
                              void* d_out, int out_size) {
    const float* x    = (const float*)d_in[0];
    const int*   ei   = (const int*)d_in[1];      // int32
    const float* Wlin = (const float*)d_in[2];
    const float* blin = (const float*)d_in[3];
    const float* Wst  = (const float*)d_in[4];
    const float* bst  = (const float*)d_in[5];
    const float* Wts  = (const float*)d_in[6];
    const float* bts  = (const float*)d_in[7];
    float* out = (float*)d_out;
    int N = in_sizes[0] / DK;
    int E = in_sizes[1] / 2;

    zero_kernel<<<1024, 256>>>(N);

    long long total_threads = (long long)E * 32;
    int blocks = (int)((total_threads + 255) / 256);
    scatter_kernel<<<blocks, 256>>>(x, ei, E);

    int ip_n = (3 * DK * DK > NMAX) ? 3 * DK * DK : NMAX;
    inv_prep_kernel<<<(ip_n + 255) / 256, 256>>>(N, Wlin, Wst, Wts, blin, bst, bts);

    cudaFuncSetAttribute(gemm_mma_kernel, cudaFuncAttributeMaxDynamicSharedMemorySize, SM_TOT);
    gemm_mma_kernel<<<(N + MT - 1) / MT, GT, SM_TOT>>>(x, out, N);
}